// round 10
// baseline (speedup 1.0000x reference)
#include <cuda_runtime.h>
#include <math.h>

// Problem dims
#define LC 512   // sequence length
#define NB 64    // batch
#define HD 512   // hidden = input size
#define RG 32    // scan CTAs (2 batch rows each)
#define RT 512   // threads per scan CTA
#define BPC 2    // batch rows per CTA

// ---------------- device scratch (module-load allocations, legal) ---------
__device__ float g_A0[LC * NB * HD];   // x @ Wih0^T + bih0 + bhh0
__device__ float g_H0[LC * NB * HD];   // all layer-0 hidden states
__device__ float g_X1[LC * NB * HD];   // H0 @ Wih1^T + bih1 + bhh1

// ---------------- precompute GEMM (validated in R7): ----------------------
// A[m][j] = sum_i X[m][i]*W[j][i] + bih[j] + bhh[j]
// X: (LC*NB, 512) row-major, W: (512, 512) row-major. 64x64x16 tile, 4x4 micro.
__global__ __launch_bounds__(256) void gemm_xW_kernel(
    const float* __restrict__ X, const float* __restrict__ W,
    const float* __restrict__ bih, const float* __restrict__ bhh,
    float* __restrict__ A0)
{
    __shared__ float As[16][68];  // As[k][m]
    __shared__ float Ws[16][68];  // Ws[k][j]

    const int m0 = blockIdx.y * 64;
    const int j0 = blockIdx.x * 64;
    const int tid = threadIdx.x;
    const int tx = tid & 15;   // j quad
    const int ty = tid >> 4;   // m quad

    float acc[4][4];
#pragma unroll
    for (int i = 0; i < 4; i++)
#pragma unroll
        for (int j = 0; j < 4; j++) acc[i][j] = 0.0f;

    const int r = tid >> 2;    // 0..63
    const int q = tid & 3;     // 0..3

    for (int k0 = 0; k0 < HD; k0 += 16) {
        float4 av = *(const float4*)&X[(m0 + r) * HD + k0 + q * 4];
        float4 wv = *(const float4*)&W[(j0 + r) * HD + k0 + q * 4];
        As[q * 4 + 0][r] = av.x; As[q * 4 + 1][r] = av.y;
        As[q * 4 + 2][r] = av.z; As[q * 4 + 3][r] = av.w;
        Ws[q * 4 + 0][r] = wv.x; Ws[q * 4 + 1][r] = wv.y;
        Ws[q * 4 + 2][r] = wv.z; Ws[q * 4 + 3][r] = wv.w;
        __syncthreads();
#pragma unroll
        for (int k = 0; k < 16; k++) {
            float4 a4 = *(const float4*)&As[k][ty * 4];
            float4 w4 = *(const float4*)&Ws[k][tx * 4];
            float am[4] = {a4.x, a4.y, a4.z, a4.w};
            float wn[4] = {w4.x, w4.y, w4.z, w4.w};
#pragma unroll
            for (int i = 0; i < 4; i++)
#pragma unroll
                for (int j = 0; j < 4; j++)
                    acc[i][j] = fmaf(am[i], wn[j], acc[i][j]);
        }
        __syncthreads();
    }

    float b[4];
#pragma unroll
    for (int j = 0; j < 4; j++) {
        int jj = j0 + tx * 4 + j;
        b[j] = bih[jj] + bhh[jj];
    }
#pragma unroll
    for (int i = 0; i < 4; i++) {
        float4 o = make_float4(acc[i][0] + b[0], acc[i][1] + b[1],
                               acc[i][2] + b[2], acc[i][3] + b[3]);
        *(float4*)&A0[(m0 + ty * 4 + i) * HD + j0 + tx * 4] = o;
    }
}

// ---------------- batch-private recurrent scan ----------------------------
// h(t)[n][j] = tanh(Apre[t][n][j] + sum_k W[j][k] * h(t-1)[n][k])
// CTA owns batch rows n0, n0+1; h lives in smem for all 512 steps.
// Thread map: warp w (0..15), lane = c2*16 + q (c2 in {0,1}, q in 0..15).
//   colw = w*2 + c2 in 0..31.  For col-block cb (0..15): col = cb*32 + colw.
//   Lane's k-slice: float4 indices k4 = q + 16*ki, ki = 0..7 (32 k values).
//   => per (col, batch): 16 q-lanes partition k; shfl-xor reduce over 16 lanes.
//   Writer: lane keeps cb == q  -> writes col mycol = q*32 + colw (bijection).
__global__ __launch_bounds__(RT)
void rnn_pass_kernel(const float* __restrict__ W,      // (512,512) row-major
                     const float* __restrict__ Apre,   // (LC*NB, HD)
                     float* __restrict__ Hout,         // (LC*NB, HD)
                     const float* __restrict__ hinit,  // (NB, HD)
                     float* __restrict__ hn)           // (NB, HD)
{
    __shared__ float hs[BPC][HD];   // current hidden state (CTA-private!)
    __shared__ float as[BPC][HD];   // staged Apre row for this step

    const int tid  = threadIdx.x;
    const int n0   = blockIdx.x * BPC;
    const int w    = tid >> 5;
    const int lane = tid & 31;
    const int c2   = lane >> 4;
    const int q    = lane & 15;
    const int colw = w * 2 + c2;          // 0..31
    const int mycol = q * 32 + colw;      // col this thread writes

    const float4* W4 = (const float4*)W;

    // init h from hinit (coalesced)
#pragma unroll
    for (int r = 0; r < BPC; r++)
        hs[r][tid] = __ldg(&hinit[(n0 + r) * HD + tid]);
    __syncthreads();

    for (int t = 0; t < LC; t++) {
        // stage this step's Apre rows (consumed after the mid-step barrier)
#pragma unroll
        for (int r = 0; r < BPC; r++)
            as[r][tid] = __ldg(&Apre[((size_t)t * NB + n0 + r) * HD + tid]);

        // accumulate: acc[b][cb] = partial dot over this lane's 32 k's
        float acc0[16], acc1[16];
#pragma unroll
        for (int cb = 0; cb < 16; cb++) { acc0[cb] = 0.f; acc1[cb] = 0.f; }

        const float4* h0v = (const float4*)&hs[0][0];
        const float4* h1v = (const float4*)&hs[1][0];
#pragma unroll
        for (int ki = 0; ki < 8; ki++) {
            const int k4 = q + 16 * ki;
            float4 ha = h0v[k4];          // LDS broadcast (16 distinct addrs)
            float4 hb = h1v[k4];
#pragma unroll
            for (int cb = 0; cb < 16; cb++) {
                // warp-coalesced: lanes cover 2 cols x 16 consecutive float4
                float4 wv = __ldg(&W4[(cb * 32 + colw) * 128 + k4]);
                acc0[cb] = fmaf(wv.x, ha.x, acc0[cb]);
                acc0[cb] = fmaf(wv.y, ha.y, acc0[cb]);
                acc0[cb] = fmaf(wv.z, ha.z, acc0[cb]);
                acc0[cb] = fmaf(wv.w, ha.w, acc0[cb]);
                acc1[cb] = fmaf(wv.x, hb.x, acc1[cb]);
                acc1[cb] = fmaf(wv.y, hb.y, acc1[cb]);
                acc1[cb] = fmaf(wv.z, hb.z, acc1[cb]);
                acc1[cb] = fmaf(wv.w, hb.w, acc1[cb]);
            }
        }

        // reduce across the 16 q-lanes (xor 8,4,2,1 stays inside 16-lane half)
#pragma unroll
        for (int cb = 0; cb < 16; cb++) {
#pragma unroll
            for (int s = 8; s > 0; s >>= 1) {
                acc0[cb] += __shfl_xor_sync(0xffffffffu, acc0[cb], s);
                acc1[cb] += __shfl_xor_sync(0xffffffffu, acc1[cb], s);
            }
        }
        // predicated select of cb == q (no dynamic register indexing)
        float v0 = 0.f, v1 = 0.f;
#pragma unroll
        for (int cb = 0; cb < 16; cb++)
            if (q == cb) { v0 = acc0[cb]; v1 = acc1[cb]; }

        __syncthreads();   // all hs reads done AND as staging visible
        float o0 = tanhf(v0 + as[0][mycol]);
        float o1 = tanhf(v1 + as[1][mycol]);
        hs[0][mycol] = o0;
        hs[1][mycol] = o1;
        __syncthreads();   // new h complete

        // coalesced flush of h(t) to global
#pragma unroll
        for (int r = 0; r < BPC; r++)
            Hout[((size_t)t * NB + n0 + r) * HD + tid] = hs[r][tid];
        if (t == LC - 1) {
#pragma unroll
            for (int r = 0; r < BPC; r++)
                hn[(n0 + r) * HD + tid] = hs[r][tid];
        }
    }
}

// ---------------- launch: 4 plain nodes ----------------------------------
extern "C" void kernel_launch(void* const* d_in, const int* in_sizes, int n_in,
                              void* d_out, int out_size) {
    const float* input  = (const float*)d_in[0];
    const float* h_0    = (const float*)d_in[1];
    const float* Wih0   = (const float*)d_in[2];
    const float* Whh0   = (const float*)d_in[3];
    const float* bih0   = (const float*)d_in[4];
    const float* bhh0   = (const float*)d_in[5];
    const float* Wih1   = (const float*)d_in[6];
    const float* Whh1   = (const float*)d_in[7];
    const float* bih1   = (const float*)d_in[8];
    const float* bhh1   = (const float*)d_in[9];
    float* out = (float*)d_out;

    float* hn0 = out + (size_t)LC * NB * HD;            // h_n layer 0
    float* hn1 = hn0 + NB * HD;                          // h_n layer 1

    dim3 ggrid(HD / 64, (LC * NB) / 64);                 // (8, 512)

    // 1) A0 = x @ Wih0^T + bih0 + bhh0   (parallel)
    gemm_xW_kernel<<<ggrid, 256>>>(input, Wih0, bih0, bhh0, g_A0);

    // 2) layer-0 scan: h0(t) = tanh(A0[t] + Whh0 h0(t-1)); stores all h0(t)
    rnn_pass_kernel<<<RG, RT>>>(Whh0, g_A0, g_H0, h_0, hn0);

    // 3) X1 = H0 @ Wih1^T + bih1 + bhh1  (parallel)
    gemm_xW_kernel<<<ggrid, 256>>>(g_H0, Wih1, bih1, bhh1, g_X1);

    // 4) layer-1 scan: h1(t) = tanh(X1[t] + Whh1 h1(t-1)); writes `out` rows
    rnn_pass_kernel<<<RG, RT>>>(Whh1, g_X1, out, h_0 + NB * HD, hn1);
}

// round 11
// speedup vs baseline: 1.0352x; 1.0352x over previous
#include <cuda_runtime.h>
#include <math.h>

// Problem dims
#define LC 512   // sequence length
#define NB 64    // batch
#define HD 512   // hidden = input size
#define RG 32    // scan CTAs (2 batch rows each)
#define RT 512   // threads per scan CTA
#define BPC 2    // batch rows per CTA

// ---------------- f32x2 packed-FMA helpers (sm_103a FFMA2) ----------------
union U64F2 {
    unsigned long long u;
    float2 f;
};

__device__ __forceinline__ void ffma2(unsigned long long& d,
                                      unsigned long long a,
                                      unsigned long long b) {
    asm("fma.rn.f32x2 %0, %1, %2, %0;" : "+l"(d) : "l"(a), "l"(b));
}

__device__ __forceinline__ unsigned long long dupf(float a) {
    unsigned long long d;
    unsigned int ai = __float_as_uint(a);
    asm("mov.b64 %0, {%1, %1};" : "=l"(d) : "r"(ai));
    return d;
}

// ---------------- device scratch (module-load allocations, legal) ---------
__device__ float g_A0[LC * NB * HD];   // x @ Wih0^T + bih0 + bhh0
__device__ float g_H0[LC * NB * HD];   // all layer-0 hidden states
__device__ float g_X1[LC * NB * HD];   // H0 @ Wih1^T + bih1 + bhh1

// ---------------- precompute GEMM (validated R7/R10, now FFMA2): ----------
// A[m][j] = sum_i X[m][i]*W[j][i] + bih[j] + bhh[j]
// X: (LC*NB, 512) row-major, W: (512, 512) row-major. 64x64x16 tile, 4x4 micro.
__global__ __launch_bounds__(256) void gemm_xW_kernel(
    const float* __restrict__ X, const float* __restrict__ W,
    const float* __restrict__ bih, const float* __restrict__ bhh,
    float* __restrict__ A0)
{
    __shared__ __align__(16) float As[16][68];  // As[k][m]
    __shared__ __align__(16) float Ws[16][68];  // Ws[k][j]

    const int m0 = blockIdx.y * 64;
    const int j0 = blockIdx.x * 64;
    const int tid = threadIdx.x;
    const int tx = tid & 15;   // j quad
    const int ty = tid >> 4;   // m quad

    // acc pairs: accp[i][jp] = (acc[i][2jp], acc[i][2jp+1])
    unsigned long long accp[4][2];
#pragma unroll
    for (int i = 0; i < 4; i++) { accp[i][0] = 0ULL; accp[i][1] = 0ULL; }

    const int r = tid >> 2;    // 0..63
    const int q = tid & 3;     // 0..3

    for (int k0 = 0; k0 < HD; k0 += 16) {
        float4 av = *(const float4*)&X[(m0 + r) * HD + k0 + q * 4];
        float4 wv = *(const float4*)&W[(j0 + r) * HD + k0 + q * 4];
        As[q * 4 + 0][r] = av.x; As[q * 4 + 1][r] = av.y;
        As[q * 4 + 2][r] = av.z; As[q * 4 + 3][r] = av.w;
        Ws[q * 4 + 0][r] = wv.x; Ws[q * 4 + 1][r] = wv.y;
        Ws[q * 4 + 2][r] = wv.z; Ws[q * 4 + 3][r] = wv.w;
        __syncthreads();
#pragma unroll
        for (int k = 0; k < 16; k++) {
            float4 a4 = *(const float4*)&As[k][ty * 4];
            ulonglong2 w2 = *(const ulonglong2*)&Ws[k][tx * 4];
            unsigned long long am[4] = {dupf(a4.x), dupf(a4.y),
                                        dupf(a4.z), dupf(a4.w)};
#pragma unroll
            for (int i = 0; i < 4; i++) {
                ffma2(accp[i][0], am[i], w2.x);
                ffma2(accp[i][1], am[i], w2.y);
            }
        }
        __syncthreads();
    }

    float b[4];
#pragma unroll
    for (int j = 0; j < 4; j++) {
        int jj = j0 + tx * 4 + j;
        b[j] = bih[jj] + bhh[jj];
    }
#pragma unroll
    for (int i = 0; i < 4; i++) {
        U64F2 p0, p1;
        p0.u = accp[i][0];
        p1.u = accp[i][1];
        float4 o = make_float4(p0.f.x + b[0], p0.f.y + b[1],
                               p1.f.x + b[2], p1.f.y + b[3]);
        *(float4*)&A0[(m0 + ty * 4 + i) * HD + j0 + tx * 4] = o;
    }
}

// ---------------- batch-private recurrent scan (v2: FFMA2, 8-lane split) --
// h(t)[n][j] = tanh(Apre[t][n][j] + sum_k W[j][k] * h(t-1)[n][k])
// CTA owns batch rows n0, n0+1; h lives in smem for all 512 steps.
// Thread map: warp w (0..15), lane = c4*8 + q (c4 in 0..3, q in 0..7).
//   colw = w*4 + c4 in 0..63.  Col-block cb (0..7): col = cb*64 + colw.
//   Lane's k-slice: float4 indices k4 = q + 8*ki, ki = 0..15 (64 k values).
//   => per (col,batch): 8 q-lanes partition k; shfl-xor(4,2,1) reduces.
//   Writer: lane keeps cb == q -> writes col mycol = q*64 + colw (bijection).
// W loads per warp: 4 rows x 128B contiguous -> fully coalesced.
__global__ __launch_bounds__(RT)
void rnn_pass_kernel(const float* __restrict__ W,      // (512,512) row-major
                     const float* __restrict__ Apre,   // (LC*NB, HD)
                     float* __restrict__ Hout,         // (LC*NB, HD)
                     const float* __restrict__ hinit,  // (NB, HD)
                     float* __restrict__ hn)           // (NB, HD)
{
    __shared__ __align__(16) float hs[BPC][HD];   // current hidden (CTA-private)
    __shared__ __align__(16) float as[BPC][HD];   // staged Apre rows

    const int tid  = threadIdx.x;
    const int n0   = blockIdx.x * BPC;
    const int w    = tid >> 5;
    const int lane = tid & 31;
    const int c4   = lane >> 3;           // 0..3
    const int q    = lane & 7;            // 0..7
    const int colw = w * 4 + c4;          // 0..63
    const int mycol = q * 64 + colw;      // col this thread writes

    const ulonglong2* Wu = (const ulonglong2*)W;   // 16B granules of W

    // init h from hinit (coalesced)
#pragma unroll
    for (int r = 0; r < BPC; r++)
        hs[r][tid] = __ldg(&hinit[(n0 + r) * HD + tid]);
    __syncthreads();

    for (int t = 0; t < LC; t++) {
        // stage this step's Apre rows (consumed after the mid-step barrier)
#pragma unroll
        for (int r = 0; r < BPC; r++)
            as[r][tid] = __ldg(&Apre[((size_t)t * NB + n0 + r) * HD + tid]);

        // acc pairs: (even-k partial, odd-k partial) per (row, col-block)
        unsigned long long acc0[8], acc1[8];
#pragma unroll
        for (int cb = 0; cb < 8; cb++) { acc0[cb] = 0ULL; acc1[cb] = 0ULL; }

        const ulonglong2* h0u = (const ulonglong2*)&hs[0][0];
        const ulonglong2* h1u = (const ulonglong2*)&hs[1][0];
#pragma unroll
        for (int ki = 0; ki < 16; ki++) {
            const int k4 = q + 8 * ki;           // float4 index 0..127
            ulonglong2 ha = h0u[k4];             // LDS.128 broadcast
            ulonglong2 hb = h1u[k4];
#pragma unroll
            for (int cb = 0; cb < 8; cb++) {
                ulonglong2 wv = __ldg(&Wu[(cb * 64 + colw) * 128 + k4]);
                ffma2(acc0[cb], wv.x, ha.x);
                ffma2(acc0[cb], wv.y, ha.y);
                ffma2(acc1[cb], wv.x, hb.x);
                ffma2(acc1[cb], wv.y, hb.y);
            }
        }

        // horizontal merge + reduce across the 8 q-lanes (xor 4,2,1)
        float s0[8], s1[8];
#pragma unroll
        for (int cb = 0; cb < 8; cb++) {
            U64F2 t0, t1;
            t0.u = acc0[cb];
            t1.u = acc1[cb];
            s0[cb] = t0.f.x + t0.f.y;
            s1[cb] = t1.f.x + t1.f.y;
#pragma unroll
            for (int sh = 4; sh > 0; sh >>= 1) {
                s0[cb] += __shfl_xor_sync(0xffffffffu, s0[cb], sh);
                s1[cb] += __shfl_xor_sync(0xffffffffu, s1[cb], sh);
            }
        }
        // predicated select of cb == q (no dynamic register indexing)
        float v0 = 0.f, v1 = 0.f;
#pragma unroll
        for (int cb = 0; cb < 8; cb++)
            if (q == cb) { v0 = s0[cb]; v1 = s1[cb]; }

        __syncthreads();   // all hs reads done AND as staging visible
        float o0 = tanhf(v0 + as[0][mycol]);
        float o1 = tanhf(v1 + as[1][mycol]);
        hs[0][mycol] = o0;
        hs[1][mycol] = o1;
        __syncthreads();   // new h complete

        // coalesced flush of h(t) to global
#pragma unroll
        for (int r = 0; r < BPC; r++)
            Hout[((size_t)t * NB + n0 + r) * HD + tid] = hs[r][tid];
        if (t == LC - 1) {
#pragma unroll
            for (int r = 0; r < BPC; r++)
                hn[(n0 + r) * HD + tid] = hs[r][tid];
        }
    }
}

// ---------------- launch: 4 plain nodes ----------------------------------
extern "C" void kernel_launch(void* const* d_in, const int* in_sizes, int n_in,
                              void* d_out, int out_size) {
    const float* input  = (const float*)d_in[0];
    const float* h_0    = (const float*)d_in[1];
    const float* Wih0   = (const float*)d_in[2];
    const float* Whh0   = (const float*)d_in[3];
    const float* bih0   = (const float*)d_in[4];
    const float* bhh0   = (const float*)d_in[5];
    const float* Wih1   = (const float*)d_in[6];
    const float* Whh1   = (const float*)d_in[7];
    const float* bih1   = (const float*)d_in[8];
    const float* bhh1   = (const float*)d_in[9];
    float* out = (float*)d_out;

    float* hn0 = out + (size_t)LC * NB * HD;            // h_n layer 0
    float* hn1 = hn0 + NB * HD;                          // h_n layer 1

    dim3 ggrid(HD / 64, (LC * NB) / 64);                 // (8, 512)

    // 1) A0 = x @ Wih0^T + bih0 + bhh0   (parallel)
    gemm_xW_kernel<<<ggrid, 256>>>(input, Wih0, bih0, bhh0, g_A0);

    // 2) layer-0 scan: h0(t) = tanh(A0[t] + Whh0 h0(t-1)); stores all h0(t)
    rnn_pass_kernel<<<RG, RT>>>(Whh0, g_A0, g_H0, h_0, hn0);

    // 3) X1 = H0 @ Wih1^T + bih1 + bhh1  (parallel)
    gemm_xW_kernel<<<ggrid, 256>>>(g_H0, Wih1, bih1, bhh1, g_X1);

    // 4) layer-1 scan: h1(t) = tanh(X1[t] + Whh1 h1(t-1)); writes `out` rows
    rnn_pass_kernel<<<RG, RT>>>(Whh1, g_X1, out, h_0 + NB * HD, hn1);
}

// round 12
// speedup vs baseline: 1.0998x; 1.0624x over previous
#include <cuda_runtime.h>
#include <math.h>

// Problem dims
#define LC 512   // sequence length
#define NB 64    // batch
#define HD 512   // hidden = input size
#define RG 32    // scan CTAs (2 batch rows each)
#define RT 512   // threads per scan CTA
#define BPC 2    // batch rows per CTA

// ---------------- f32x2 packed-FMA helpers (sm_103a FFMA2) ----------------
union U64F2 {
    unsigned long long u;
    float2 f;
};

__device__ __forceinline__ void ffma2(unsigned long long& d,
                                      unsigned long long a,
                                      unsigned long long b) {
    asm("fma.rn.f32x2 %0, %1, %2, %0;" : "+l"(d) : "l"(a), "l"(b));
}

__device__ __forceinline__ unsigned long long dupf(float a) {
    unsigned long long d;
    unsigned int ai = __float_as_uint(a);
    asm("mov.b64 %0, {%1, %1};" : "=l"(d) : "r"(ai));
    return d;
}

// ---------------- device scratch (module-load allocations, legal) ---------
__device__ float g_A0[LC * NB * HD];   // x @ Wih0^T + bih0 + bhh0
__device__ float g_H0[LC * NB * HD];   // all layer-0 hidden states
__device__ float g_X1[LC * NB * HD];   // H0 @ Wih1^T + bih1 + bhh1

// ---------------- precompute GEMM (validated R7/R10/R11): -----------------
// A[m][j] = sum_i X[m][i]*W[j][i] + bih[j] + bhh[j]
__global__ __launch_bounds__(256) void gemm_xW_kernel(
    const float* __restrict__ X, const float* __restrict__ W,
    const float* __restrict__ bih, const float* __restrict__ bhh,
    float* __restrict__ A0)
{
    __shared__ __align__(16) float As[16][68];  // As[k][m]
    __shared__ __align__(16) float Ws[16][68];  // Ws[k][j]

    const int m0 = blockIdx.y * 64;
    const int j0 = blockIdx.x * 64;
    const int tid = threadIdx.x;
    const int tx = tid & 15;   // j quad
    const int ty = tid >> 4;   // m quad

    unsigned long long accp[4][2];
#pragma unroll
    for (int i = 0; i < 4; i++) { accp[i][0] = 0ULL; accp[i][1] = 0ULL; }

    const int r = tid >> 2;    // 0..63
    const int q = tid & 3;     // 0..3

    for (int k0 = 0; k0 < HD; k0 += 16) {
        float4 av = *(const float4*)&X[(m0 + r) * HD + k0 + q * 4];
        float4 wv = *(const float4*)&W[(j0 + r) * HD + k0 + q * 4];
        As[q * 4 + 0][r] = av.x; As[q * 4 + 1][r] = av.y;
        As[q * 4 + 2][r] = av.z; As[q * 4 + 3][r] = av.w;
        Ws[q * 4 + 0][r] = wv.x; Ws[q * 4 + 1][r] = wv.y;
        Ws[q * 4 + 2][r] = wv.z; Ws[q * 4 + 3][r] = wv.w;
        __syncthreads();
#pragma unroll
        for (int k = 0; k < 16; k++) {
            float4 a4 = *(const float4*)&As[k][ty * 4];
            ulonglong2 w2 = *(const ulonglong2*)&Ws[k][tx * 4];
            unsigned long long am[4] = {dupf(a4.x), dupf(a4.y),
                                        dupf(a4.z), dupf(a4.w)};
#pragma unroll
            for (int i = 0; i < 4; i++) {
                ffma2(accp[i][0], am[i], w2.x);
                ffma2(accp[i][1], am[i], w2.y);
            }
        }
        __syncthreads();
    }

    float b[4];
#pragma unroll
    for (int j = 0; j < 4; j++) {
        int jj = j0 + tx * 4 + j;
        b[j] = bih[jj] + bhh[jj];
    }
#pragma unroll
    for (int i = 0; i < 4; i++) {
        U64F2 p0, p1;
        p0.u = accp[i][0];
        p1.u = accp[i][1];
        float4 o = make_float4(p0.f.x + b[0], p0.f.y + b[1],
                               p1.f.x + b[2], p1.f.y + b[3]);
        *(float4*)&A0[(m0 + ty * 4 + i) * HD + j0 + tx * 4] = o;
    }
}

// ---------------- batch-private recurrent scan (v3) -----------------------
// h(t)[n][j] = tanh(Apre[t][n][j] + sum_k W[j][k] * h(t-1)[n][k])
// v3 changes vs validated v2:
//  * hs ping-pong (read hs[b], write hs[b^1]) -> ONE __syncthreads per step.
//    Safety: step t reads hs[b] (all reads precede the barrier), writes
//    hs[b^1]; step t+1 reads hs[b^1], writes hs[b]. Writes to hs[b] at t+1
//    only conflict with reads of hs[b] at t, which the barrier orders. The
//    post-barrier flush reads hs[b^1] (the buffer NOT written next step).
//  * Apre staged in registers (each thread only needs column mycol), with
//    next step's values prefetched at the top of the current step.
// Thread map (validated v2): warp w (0..15), lane = c4*8 + q.
//   colw = w*4 + c4 (0..63); col-block cb (0..7): col = cb*64 + colw.
//   Lane k-slice: float4 k4 = q + 8*ki, ki 0..15. shfl-xor(4,2,1) reduces
//   over the 8 q-lanes; lane keeps cb == q -> writes mycol = q*64 + colw.
__global__ __launch_bounds__(RT)
void rnn_pass_kernel(const float* __restrict__ W,      // (512,512) row-major
                     const float* __restrict__ Apre,   // (LC*NB, HD)
                     float* __restrict__ Hout,         // (LC*NB, HD)
                     const float* __restrict__ hinit,  // (NB, HD)
                     float* __restrict__ hn)           // (NB, HD)
{
    __shared__ __align__(16) float hs[2][BPC][HD];   // ping-pong hidden state

    const int tid  = threadIdx.x;
    const int n0   = blockIdx.x * BPC;
    const int w    = tid >> 5;
    const int lane = tid & 31;
    const int c4   = lane >> 3;           // 0..3
    const int q    = lane & 7;            // 0..7
    const int colw = w * 4 + c4;          // 0..63
    const int mycol = q * 64 + colw;      // col this thread writes

    const ulonglong2* Wu = (const ulonglong2*)W;   // 16B granules of W

    // init h(-1) into buffer 0 (coalesced)
#pragma unroll
    for (int r = 0; r < BPC; r++)
        hs[0][r][tid] = __ldg(&hinit[(n0 + r) * HD + tid]);

    // preload Apre for t=0 (per-thread own column)
    float a0 = __ldg(&Apre[(size_t)(n0 + 0) * HD + mycol]);
    float a1 = __ldg(&Apre[(size_t)(n0 + 1) * HD + mycol]);
    __syncthreads();

    int b = 0;
    for (int t = 0; t < LC; t++) {
        // prefetch next step's Apre early (independent of everything below)
        const int tn = (t + 1 < LC) ? (t + 1) : t;
        float p0 = __ldg(&Apre[((size_t)tn * NB + n0 + 0) * HD + mycol]);
        float p1 = __ldg(&Apre[((size_t)tn * NB + n0 + 1) * HD + mycol]);

        // acc pairs: (even-k partial, odd-k partial) per (row, col-block)
        unsigned long long acc0[8], acc1[8];
#pragma unroll
        for (int cb = 0; cb < 8; cb++) { acc0[cb] = 0ULL; acc1[cb] = 0ULL; }

        const ulonglong2* h0u = (const ulonglong2*)&hs[b][0][0];
        const ulonglong2* h1u = (const ulonglong2*)&hs[b][1][0];
#pragma unroll
        for (int ki = 0; ki < 16; ki++) {
            const int k4 = q + 8 * ki;           // float4 index 0..127
            ulonglong2 ha = h0u[k4];             // LDS.128 broadcast
            ulonglong2 hb = h1u[k4];
#pragma unroll
            for (int cb = 0; cb < 8; cb++) {
                ulonglong2 wv = __ldg(&Wu[(cb * 64 + colw) * 128 + k4]);
                ffma2(acc0[cb], wv.x, ha.x);
                ffma2(acc0[cb], wv.y, ha.y);
                ffma2(acc1[cb], wv.x, hb.x);
                ffma2(acc1[cb], wv.y, hb.y);
            }
        }

        // horizontal merge + reduce across the 8 q-lanes (xor 4,2,1)
        float s0[8], s1[8];
#pragma unroll
        for (int cb = 0; cb < 8; cb++) {
            U64F2 t0, t1;
            t0.u = acc0[cb];
            t1.u = acc1[cb];
            s0[cb] = t0.f.x + t0.f.y;
            s1[cb] = t1.f.x + t1.f.y;
#pragma unroll
            for (int sh = 4; sh > 0; sh >>= 1) {
                s0[cb] += __shfl_xor_sync(0xffffffffu, s0[cb], sh);
                s1[cb] += __shfl_xor_sync(0xffffffffu, s1[cb], sh);
            }
        }
        // predicated select of cb == q (no dynamic register indexing)
        float v0 = 0.f, v1 = 0.f;
#pragma unroll
        for (int cb = 0; cb < 8; cb++)
            if (q == cb) { v0 = s0[cb]; v1 = s1[cb]; }

        float o0 = tanhf(v0 + a0);
        float o1 = tanhf(v1 + a1);
        a0 = p0; a1 = p1;                 // rotate prefetched Apre
        hs[b ^ 1][0][mycol] = o0;
        hs[b ^ 1][1][mycol] = o1;
        __syncthreads();                  // the ONLY barrier in the step

        // coalesced flush of h(t) to global (reads the just-written buffer,
        // which the next step does NOT write)
#pragma unroll
        for (int r = 0; r < BPC; r++)
            Hout[((size_t)t * NB + n0 + r) * HD + tid] = hs[b ^ 1][r][tid];
        if (t == LC - 1) {
#pragma unroll
            for (int r = 0; r < BPC; r++)
                hn[(n0 + r) * HD + tid] = hs[b ^ 1][r][tid];
        }
        b ^= 1;
    }
}

// ---------------- launch: 4 plain nodes ----------------------------------
extern "C" void kernel_launch(void* const* d_in, const int* in_sizes, int n_in,
                              void* d_out, int out_size) {
    const float* input  = (const float*)d_in[0];
    const float* h_0    = (const float*)d_in[1];
    const float* Wih0   = (const float*)d_in[2];
    const float* Whh0   = (const float*)d_in[3];
    const float* bih0   = (const float*)d_in[4];
    const float* bhh0   = (const float*)d_in[5];
    const float* Wih1   = (const float*)d_in[6];
    const float* Whh1   = (const float*)d_in[7];
    const float* bih1   = (const float*)d_in[8];
    const float* bhh1   = (const float*)d_in[9];
    float* out = (float*)d_out;

    float* hn0 = out + (size_t)LC * NB * HD;            // h_n layer 0
    float* hn1 = hn0 + NB * HD;                          // h_n layer 1

    dim3 ggrid(HD / 64, (LC * NB) / 64);                 // (8, 512)

    // 1) A0 = x @ Wih0^T + bih0 + bhh0   (parallel)
    gemm_xW_kernel<<<ggrid, 256>>>(input, Wih0, bih0, bhh0, g_A0);

    // 2) layer-0 scan: h0(t) = tanh(A0[t] + Whh0 h0(t-1)); stores all h0(t)
    rnn_pass_kernel<<<RG, RT>>>(Whh0, g_A0, g_H0, h_0, hn0);

    // 3) X1 = H0 @ Wih1^T + bih1 + bhh1  (parallel)
    gemm_xW_kernel<<<ggrid, 256>>>(g_H0, Wih1, bih1, bhh1, g_X1);

    // 4) layer-1 scan: h1(t) = tanh(X1[t] + Whh1 h1(t-1)); writes `out` rows
    rnn_pass_kernel<<<RG, RT>>>(Whh1, g_X1, out, h_0 + NB * HD, hn1);
}

// round 13
// speedup vs baseline: 1.4008x; 1.2737x over previous
#include <cuda_runtime.h>
#include <math.h>

// Problem dims
#define LC 512   // sequence length
#define NB 64    // batch
#define HD 512   // hidden = input size
#define CSZ 4    // cluster size (CTAs per cluster)
#define RG 64    // scan CTAs total: 16 clusters x 4 CTAs
#define RT 512   // threads per scan CTA
#define RPC 4    // batch rows per cluster
#define COLS_PER_CTA 128

// ---------------- f32x2 packed-FMA helpers (sm_103a FFMA2) ----------------
union U64F2 {
    unsigned long long u;
    float2 f;
};

__device__ __forceinline__ void ffma2(unsigned long long& d,
                                      unsigned long long a,
                                      unsigned long long b) {
    asm("fma.rn.f32x2 %0, %1, %2, %0;" : "+l"(d) : "l"(a), "l"(b));
}

__device__ __forceinline__ unsigned long long dupf(float a) {
    unsigned long long d;
    unsigned int ai = __float_as_uint(a);
    asm("mov.b64 %0, {%1, %1};" : "=l"(d) : "r"(ai));
    return d;
}

// ---------------- cluster helpers ----------------------------------------
__device__ __forceinline__ unsigned int ctarank() {
    unsigned int r;
    asm("mov.u32 %0, %%cluster_ctarank;" : "=r"(r));
    return r;
}

__device__ __forceinline__ unsigned int smem_u32(const void* p) {
    unsigned int a;
    asm("{ .reg .u64 t; cvta.to.shared.u64 t, %1; cvt.u32.u64 %0, t; }"
        : "=r"(a) : "l"(p));
    return a;
}

// store 4B to the same smem offset in cluster CTA `rank`
__device__ __forceinline__ void st_cluster_f32(unsigned int saddr,
                                               unsigned int rank, float v) {
    unsigned int ra;
    asm volatile("mapa.shared::cluster.u32 %0, %1, %2;"
                 : "=r"(ra) : "r"(saddr), "r"(rank));
    asm volatile("st.shared::cluster.f32 [%0], %1;" :: "r"(ra), "f"(v)
                 : "memory");
}

__device__ __forceinline__ void cluster_sync() {
    asm volatile("barrier.cluster.arrive.aligned;" ::: "memory");
    asm volatile("barrier.cluster.wait.aligned;" ::: "memory");
}

// ---------------- device scratch (module-load allocations, legal) ---------
__device__ float g_A0[LC * NB * HD];   // x @ Wih0^T + bih0 + bhh0
__device__ float g_H0[LC * NB * HD];   // all layer-0 hidden states
__device__ float g_X1[LC * NB * HD];   // H0 @ Wih1^T + bih1 + bhh1

// ---------------- precompute GEMM (validated R7/R10-R12): -----------------
// A[m][j] = sum_i X[m][i]*W[j][i] + bih[j] + bhh[j]
__global__ __launch_bounds__(256) void gemm_xW_kernel(
    const float* __restrict__ X, const float* __restrict__ W,
    const float* __restrict__ bih, const float* __restrict__ bhh,
    float* __restrict__ A0)
{
    __shared__ __align__(16) float As[16][68];  // As[k][m]
    __shared__ __align__(16) float Ws[16][68];  // Ws[k][j]

    const int m0 = blockIdx.y * 64;
    const int j0 = blockIdx.x * 64;
    const int tid = threadIdx.x;
    const int tx = tid & 15;   // j quad
    const int ty = tid >> 4;   // m quad

    unsigned long long accp[4][2];
#pragma unroll
    for (int i = 0; i < 4; i++) { accp[i][0] = 0ULL; accp[i][1] = 0ULL; }

    const int r = tid >> 2;    // 0..63
    const int q = tid & 3;     // 0..3

    for (int k0 = 0; k0 < HD; k0 += 16) {
        float4 av = *(const float4*)&X[(m0 + r) * HD + k0 + q * 4];
        float4 wv = *(const float4*)&W[(j0 + r) * HD + k0 + q * 4];
        As[q * 4 + 0][r] = av.x; As[q * 4 + 1][r] = av.y;
        As[q * 4 + 2][r] = av.z; As[q * 4 + 3][r] = av.w;
        Ws[q * 4 + 0][r] = wv.x; Ws[q * 4 + 1][r] = wv.y;
        Ws[q * 4 + 2][r] = wv.z; Ws[q * 4 + 3][r] = wv.w;
        __syncthreads();
#pragma unroll
        for (int k = 0; k < 16; k++) {
            float4 a4 = *(const float4*)&As[k][ty * 4];
            ulonglong2 w2 = *(const ulonglong2*)&Ws[k][tx * 4];
            unsigned long long am[4] = {dupf(a4.x), dupf(a4.y),
                                        dupf(a4.z), dupf(a4.w)};
#pragma unroll
            for (int i = 0; i < 4; i++) {
                ffma2(accp[i][0], am[i], w2.x);
                ffma2(accp[i][1], am[i], w2.y);
            }
        }
        __syncthreads();
    }

    float b[4];
#pragma unroll
    for (int j = 0; j < 4; j++) {
        int jj = j0 + tx * 4 + j;
        b[j] = bih[jj] + bhh[jj];
    }
#pragma unroll
    for (int i = 0; i < 4; i++) {
        U64F2 p0, p1;
        p0.u = accp[i][0];
        p1.u = accp[i][1];
        float4 o = make_float4(p0.f.x + b[0], p0.f.y + b[1],
                               p1.f.x + b[2], p1.f.y + b[3]);
        *(float4*)&A0[(m0 + ty * 4 + i) * HD + j0 + tx * 4] = o;
    }
}

// ---------------- clustered recurrent scan (v4) ---------------------------
// h(t)[n][j] = tanh(Apre[t][n][j] + sum_k W[j][k] * h(t-1)[n][k])
// 16 clusters x 4 CTAs. Cluster owns batch rows n0..n0+3 (n0 = cluster*4).
// CTA rank r owns output columns [r*128, (r+1)*128) -> streams only 256KB
// of W per step (floor 2048 cyc vs 8192 unsplit). Full h replicated in each
// CTA's smem; after computing its 4x128 block each thread stores its output
// to all 4 CTAs' hs[b^1] via mapa/st.shared::cluster, then cluster barrier
// (arrive=release, wait=acquire) publishes the DSMEM writes.
//
// Thread map (R12-validated, reparameterized): w = tid>>5, lane = c4*8+q.
//   colw = w*4+c4 (0..63); col-block cb (0..1): local col = cb*64+colw.
//   Lane k-slice: float4 granules k4 = q+8*ki, ki 0..15 (64 k's/lane).
//   shfl-xor(4,2,1) reduces the 8 q-lanes; lane q keeps output
//   (row = q>>1, cb = q&1) -> one output/thread (bijection over 4x128).
__global__ __launch_bounds__(RT) __cluster_dims__(CSZ, 1, 1)
void rnn_pass_kernel(const float* __restrict__ W,      // (512,512) row-major
                     const float* __restrict__ Apre,   // (LC*NB, HD)
                     float* __restrict__ Hout,         // (LC*NB, HD)
                     const float* __restrict__ hinit,  // (NB, HD)
                     float* __restrict__ hn)           // (NB, HD)
{
    __shared__ __align__(16) float hs[2][RPC][HD];   // ping-pong full h (16KB)

    const int tid  = threadIdx.x;
    const unsigned int rank = ctarank();             // 0..3
    const int n0   = (blockIdx.x >> 2) * RPC;        // cluster's batch base
    const int slice = (int)rank * COLS_PER_CTA;      // my 128-col W slice

    const int w    = tid >> 5;
    const int lane = tid & 31;
    const int c4   = lane >> 3;            // 0..3
    const int q    = lane & 7;             // 0..7
    const int colw = w * 4 + c4;           // 0..63
    const int myrow = q >> 1;              // 0..3  (batch row in cluster)
    const int mycl  = (q & 1) * 64 + colw; // 0..127 (col within slice)
    const int gcol  = slice + mycl;        // global output column

    const ulonglong2* Wu = (const ulonglong2*)W;     // 16B granules

    // init h(-1) into buffer 0: 4 rows x 512 cols, coalesced
#pragma unroll
    for (int r = 0; r < RPC; r++) {
        int idx = tid + r * RT;            // 0..2047
        int row = idx >> 9, col = idx & 511;
        hs[0][row][col] = __ldg(&hinit[(n0 + row) * HD + col]);
    }

    // preload Apre for t=0 (per-thread own output element)
    float ac = __ldg(&Apre[(size_t)(n0 + myrow) * HD + gcol]);
    __syncthreads();

    int b = 0;
    for (int t = 0; t < LC; t++) {
        // prefetch next step's Apre (independent of everything below)
        const int tn = (t + 1 < LC) ? (t + 1) : t;
        float ap = __ldg(&Apre[((size_t)tn * NB + n0 + myrow) * HD + gcol]);

        // acc[row][cb]: packed (even,odd) k partials
        unsigned long long acc[RPC][2];
#pragma unroll
        for (int r = 0; r < RPC; r++) { acc[r][0] = 0ULL; acc[r][1] = 0ULL; }

        const ulonglong2* h0u = (const ulonglong2*)&hs[b][0][0];
        const ulonglong2* h1u = (const ulonglong2*)&hs[b][1][0];
        const ulonglong2* h2u = (const ulonglong2*)&hs[b][2][0];
        const ulonglong2* h3u = (const ulonglong2*)&hs[b][3][0];
#pragma unroll
        for (int ki = 0; ki < 16; ki++) {
            const int k4 = q + 8 * ki;               // float4 index 0..127
            ulonglong2 h0 = h0u[k4];                 // LDS.128, 8-addr bcast
            ulonglong2 h1 = h1u[k4];
            ulonglong2 h2 = h2u[k4];
            ulonglong2 h3 = h3u[k4];
#pragma unroll
            for (int cb = 0; cb < 2; cb++) {
                // W row = slice + cb*64 + colw; warp reads 4x128B lines
                ulonglong2 wv = __ldg(&Wu[(slice + cb * 64 + colw) * 128 + k4]);
                ffma2(acc[0][cb], wv.x, h0.x); ffma2(acc[0][cb], wv.y, h0.y);
                ffma2(acc[1][cb], wv.x, h1.x); ffma2(acc[1][cb], wv.y, h1.y);
                ffma2(acc[2][cb], wv.x, h2.x); ffma2(acc[2][cb], wv.y, h2.y);
                ffma2(acc[3][cb], wv.x, h3.x); ffma2(acc[3][cb], wv.y, h3.y);
            }
        }

        // merge pairs + reduce across the 8 q-lanes (xor 4,2,1)
        float v = 0.f;
#pragma unroll
        for (int r = 0; r < RPC; r++) {
#pragma unroll
            for (int cb = 0; cb < 2; cb++) {
                U64F2 m;
                m.u = acc[r][cb];
                float s = m.f.x + m.f.y;
#pragma unroll
                for (int sh = 4; sh > 0; sh >>= 1)
                    s += __shfl_xor_sync(0xffffffffu, s, sh);
                if (myrow == r && (q & 1) == cb) v = s;   // predicated keep
            }
        }

        float o = tanhf(v + ac);
        ac = ap;                            // rotate prefetched Apre

        // publish o into hs[b^1][myrow][gcol] of ALL 4 cluster CTAs
        {
            unsigned int base = smem_u32(&hs[b ^ 1][myrow][gcol]);
            hs[b ^ 1][myrow][gcol] = o;     // local copy
#pragma unroll
            for (unsigned int rr = 0; rr < CSZ; rr++)
                if (rr != rank) st_cluster_f32(base, rr, o);
        }
        cluster_sync();                     // release/acquire: h(t) complete

        // flush my slice of h(t) to global (coalesced 512B runs)
        {
            int row = tid >> 7, cl = tid & 127;
            float hv = hs[b ^ 1][row][slice + cl];
            Hout[((size_t)t * NB + n0 + row) * HD + slice + cl] = hv;
            if (t == LC - 1)
                hn[(n0 + row) * HD + slice + cl] = hv;
        }
        b ^= 1;
    }
}

// ---------------- launch: 4 plain nodes ----------------------------------
extern "C" void kernel_launch(void* const* d_in, const int* in_sizes, int n_in,
                              void* d_out, int out_size) {
    const float* input  = (const float*)d_in[0];
    const float* h_0    = (const float*)d_in[1];
    const float* Wih0   = (const float*)d_in[2];
    const float* Whh0   = (const float*)d_in[3];
    const float* bih0   = (const float*)d_in[4];
    const float* bhh0   = (const float*)d_in[5];
    const float* Wih1   = (const float*)d_in[6];
    const float* Whh1   = (const float*)d_in[7];
    const float* bih1   = (const float*)d_in[8];
    const float* bhh1   = (const float*)d_in[9];
    float* out = (float*)d_out;

    float* hn0 = out + (size_t)LC * NB * HD;            // h_n layer 0
    float* hn1 = hn0 + NB * HD;                          // h_n layer 1

    dim3 ggrid(HD / 64, (LC * NB) / 64);                 // (8, 512)

    // 1) A0 = x @ Wih0^T + bih0 + bhh0   (parallel)
    gemm_xW_kernel<<<ggrid, 256>>>(input, Wih0, bih0, bhh0, g_A0);

    // 2) layer-0 scan: h0(t) = tanh(A0[t] + Whh0 h0(t-1)); stores all h0(t)
    rnn_pass_kernel<<<RG, RT>>>(Whh0, g_A0, g_H0, h_0, hn0);

    // 3) X1 = H0 @ Wih1^T + bih1 + bhh1  (parallel)
    gemm_xW_kernel<<<ggrid, 256>>>(g_H0, Wih1, bih1, bhh1, g_X1);

    // 4) layer-1 scan: h1(t) = tanh(X1[t] + Whh1 h1(t-1)); writes `out` rows
    rnn_pass_kernel<<<RG, RT>>>(Whh1, g_X1, out, h_0 + NB * HD, hn1);
}

// round 14
// speedup vs baseline: 1.6835x; 1.2018x over previous
#include <cuda_runtime.h>
#include <math.h>

// Problem dims
#define LC 512   // sequence length
#define NB 64    // batch
#define HD 512   // hidden = input size
#define CSZ 4    // cluster size (CTAs per cluster)
#define RG 64    // scan CTAs total: 16 clusters x 4 CTAs
#define RT 512   // threads per scan CTA
#define RPC 4    // batch rows per cluster
#define COLS_PER_CTA 128

// ---------------- f32x2 packed-FMA helpers (sm_103a FFMA2) ----------------
union U64F2 {
    unsigned long long u;
    float2 f;
};

__device__ __forceinline__ void ffma2(unsigned long long& d,
                                      unsigned long long a,
                                      unsigned long long b) {
    asm("fma.rn.f32x2 %0, %1, %2, %0;" : "+l"(d) : "l"(a), "l"(b));
}

__device__ __forceinline__ unsigned long long dupf(float a) {
    unsigned long long d;
    unsigned int ai = __float_as_uint(a);
    asm("mov.b64 %0, {%1, %1};" : "=l"(d) : "r"(ai));
    return d;
}

// ---------------- cluster helpers ----------------------------------------
__device__ __forceinline__ unsigned int ctarank() {
    unsigned int r;
    asm("mov.u32 %0, %%cluster_ctarank;" : "=r"(r));
    return r;
}

__device__ __forceinline__ unsigned int smem_u32(const void* p) {
    unsigned int a;
    asm("{ .reg .u64 t; cvta.to.shared.u64 t, %1; cvt.u32.u64 %0, t; }"
        : "=r"(a) : "l"(p));
    return a;
}

__device__ __forceinline__ void st_cluster_f32(unsigned int saddr,
                                               unsigned int rank, float v) {
    unsigned int ra;
    asm volatile("mapa.shared::cluster.u32 %0, %1, %2;"
                 : "=r"(ra) : "r"(saddr), "r"(rank));
    asm volatile("st.shared::cluster.f32 [%0], %1;" :: "r"(ra), "f"(v)
                 : "memory");
}

__device__ __forceinline__ void cluster_sync() {
    asm volatile("barrier.cluster.arrive.aligned;" ::: "memory");
    asm volatile("barrier.cluster.wait.aligned;" ::: "memory");
}

// ---------------- device scratch (module-load allocations, legal) ---------
__device__ float g_A0[LC * NB * HD];   // x @ Wih0^T + bih0 + bhh0
__device__ float g_H0[LC * NB * HD];   // all layer-0 hidden states
__device__ float g_X1[LC * NB * HD];   // H0 @ Wih1^T + bih1 + bhh1

// ---------------- GEMM v2: 128x128 tile, 8x8 micro, double-buffered -------
// A[m][j] = sum_i X[m][i]*W[j][i] + bih[j] + bhh[j]
// X: (LC*NB, 512) row-major, W: (512, 512) row-major.
// Thread (tx 0..15, ty 0..15) owns rows {ty*4+i, 64+ty*4+i} and
// cols {tx*4+j, 64+tx*4+j} (i,j 0..3) -> LDS.128-friendly frags.
#define GK 16
__global__ __launch_bounds__(256) void gemm_xW_kernel(
    const float* __restrict__ X, const float* __restrict__ W,
    const float* __restrict__ bih, const float* __restrict__ bhh,
    float* __restrict__ A0)
{
    __shared__ __align__(16) float As[2][GK][132];  // As[buf][k][m]
    __shared__ __align__(16) float Ws[2][GK][132];  // Ws[buf][k][j]

    const int m0 = blockIdx.y * 128;
    const int j0 = blockIdx.x * 128;
    const int tid = threadIdx.x;
    const int tx = tid & 15;
    const int ty = tid >> 4;

    // staging indices: row r = tid>>1 (0..127), float4 pair c0 = (tid&1)*2
    const int r  = tid >> 1;
    const int c0 = (tid & 1) * 2;

    // acc[i][jp]: i = row idx (0..3 lo group, 4..7 hi), jp = col pair
    // (0,1): cols tx*4+{0,1},{2,3}; (2,3): cols 64+tx*4+{0,1},{2,3}
    unsigned long long acc[8][4];
#pragma unroll
    for (int i = 0; i < 8; i++)
#pragma unroll
        for (int jp = 0; jp < 4; jp++) acc[i][jp] = 0ULL;

    // prologue: stage chunk 0 into buffer 0
    {
        float4 xv0 = __ldg((const float4*)&X[(m0 + r) * HD + (c0 + 0) * 4]);
        float4 xv1 = __ldg((const float4*)&X[(m0 + r) * HD + (c0 + 1) * 4]);
        float4 wv0 = __ldg((const float4*)&W[(j0 + r) * HD + (c0 + 0) * 4]);
        float4 wv1 = __ldg((const float4*)&W[(j0 + r) * HD + (c0 + 1) * 4]);
        As[0][c0 * 4 + 0][r] = xv0.x; As[0][c0 * 4 + 1][r] = xv0.y;
        As[0][c0 * 4 + 2][r] = xv0.z; As[0][c0 * 4 + 3][r] = xv0.w;
        As[0][c0 * 4 + 4][r] = xv1.x; As[0][c0 * 4 + 5][r] = xv1.y;
        As[0][c0 * 4 + 6][r] = xv1.z; As[0][c0 * 4 + 7][r] = xv1.w;
        Ws[0][c0 * 4 + 0][r] = wv0.x; Ws[0][c0 * 4 + 1][r] = wv0.y;
        Ws[0][c0 * 4 + 2][r] = wv0.z; Ws[0][c0 * 4 + 3][r] = wv0.w;
        Ws[0][c0 * 4 + 4][r] = wv1.x; Ws[0][c0 * 4 + 5][r] = wv1.y;
        Ws[0][c0 * 4 + 6][r] = wv1.z; Ws[0][c0 * 4 + 7][r] = wv1.w;
    }
    __syncthreads();

    for (int kc = 0; kc < HD / GK; kc++) {
        const int buf = kc & 1;
        // issue next chunk's LDGs into registers (scoreboard waits at STS)
        float4 xv0, xv1, wv0, wv1;
        const bool more = (kc + 1 < HD / GK);
        if (more) {
            const int k0 = (kc + 1) * GK;
            xv0 = __ldg((const float4*)&X[(m0 + r) * HD + k0 + (c0 + 0) * 4]);
            xv1 = __ldg((const float4*)&X[(m0 + r) * HD + k0 + (c0 + 1) * 4]);
            wv0 = __ldg((const float4*)&W[(j0 + r) * HD + k0 + (c0 + 0) * 4]);
            wv1 = __ldg((const float4*)&W[(j0 + r) * HD + k0 + (c0 + 1) * 4]);
        }

        // compute on current buffer
#pragma unroll
        for (int k = 0; k < GK; k++) {
            float4 alo = *(const float4*)&As[buf][k][ty * 4];
            float4 ahi = *(const float4*)&As[buf][k][64 + ty * 4];
            ulonglong2 blo = *(const ulonglong2*)&Ws[buf][k][tx * 4];
            ulonglong2 bhi = *(const ulonglong2*)&Ws[buf][k][64 + tx * 4];
            unsigned long long am[8] = {
                dupf(alo.x), dupf(alo.y), dupf(alo.z), dupf(alo.w),
                dupf(ahi.x), dupf(ahi.y), dupf(ahi.z), dupf(ahi.w)};
#pragma unroll
            for (int i = 0; i < 8; i++) {
                ffma2(acc[i][0], am[i], blo.x);
                ffma2(acc[i][1], am[i], blo.y);
                ffma2(acc[i][2], am[i], bhi.x);
                ffma2(acc[i][3], am[i], bhi.y);
            }
        }

        // commit next chunk
        if (more) {
            const int nb = buf ^ 1;
            As[nb][c0 * 4 + 0][r] = xv0.x; As[nb][c0 * 4 + 1][r] = xv0.y;
            As[nb][c0 * 4 + 2][r] = xv0.z; As[nb][c0 * 4 + 3][r] = xv0.w;
            As[nb][c0 * 4 + 4][r] = xv1.x; As[nb][c0 * 4 + 5][r] = xv1.y;
            As[nb][c0 * 4 + 6][r] = xv1.z; As[nb][c0 * 4 + 7][r] = xv1.w;
            Ws[nb][c0 * 4 + 0][r] = wv0.x; Ws[nb][c0 * 4 + 1][r] = wv0.y;
            Ws[nb][c0 * 4 + 2][r] = wv0.z; Ws[nb][c0 * 4 + 3][r] = wv0.w;
            Ws[nb][c0 * 4 + 4][r] = wv1.x; Ws[nb][c0 * 4 + 5][r] = wv1.y;
            Ws[nb][c0 * 4 + 6][r] = wv1.z; Ws[nb][c0 * 4 + 7][r] = wv1.w;
        }
        __syncthreads();
    }

    // epilogue: add biases, store 8x8 as 16B stores
    float blo_[4], bhi_[4];
#pragma unroll
    for (int j = 0; j < 4; j++) {
        int jlo = j0 + tx * 4 + j;
        int jhi = j0 + 64 + tx * 4 + j;
        blo_[j] = __ldg(&bih[jlo]) + __ldg(&bhh[jlo]);
        bhi_[j] = __ldg(&bih[jhi]) + __ldg(&bhh[jhi]);
    }
#pragma unroll
    for (int i = 0; i < 8; i++) {
        const int m = m0 + ((i < 4) ? (ty * 4 + i) : (64 + ty * 4 + (i - 4)));
        U64F2 p0, p1, p2, p3;
        p0.u = acc[i][0]; p1.u = acc[i][1];
        p2.u = acc[i][2]; p3.u = acc[i][3];
        float4 olo = make_float4(p0.f.x + blo_[0], p0.f.y + blo_[1],
                                 p1.f.x + blo_[2], p1.f.y + blo_[3]);
        float4 ohi = make_float4(p2.f.x + bhi_[0], p2.f.y + bhi_[1],
                                 p3.f.x + bhi_[2], p3.f.y + bhi_[3]);
        *(float4*)&A0[(size_t)m * HD + j0 + tx * 4]      = olo;
        *(float4*)&A0[(size_t)m * HD + j0 + 64 + tx * 4] = ohi;
    }
}

// ---------------- clustered recurrent scan (v5: 16-lane k-split) ----------
// h(t)[n][j] = tanh(Apre[t][n][j] + sum_k W[j][k] * h(t-1)[n][k])
// 16 clusters x 4 CTAs; CTA rank owns 128 output cols (256KB W/step, L1
// floor 2048 cyc). v5: k-split widened 8 -> 16 lanes so each h granule
// feeds 4 columns -> h LDS traffic 512KB -> 256KB/step (2048 cyc), now
// balanced with (and overlapped against) the W L1 stream.
// Thread map: w = tid>>5, lane = c2*16 + q (c2 0..1, q 0..15).
//   colw = w*2 + c2 (0..31); col-block cb 0..3: local col = cb*32 + colw.
//   Lane k-slice: float4 granules k4 = q + 16*ki, ki 0..7 (32 k's).
//   shfl-xor(8,4,2,1) reduces the 16 q-lanes; lane q keeps output
//   (row = q>>2, cb = q&3) -> one output/thread (bijection over 4x128).
__global__ __launch_bounds__(RT) __cluster_dims__(CSZ, 1, 1)
void rnn_pass_kernel(const float* __restrict__ W,      // (512,512) row-major
                     const float* __restrict__ Apre,   // (LC*NB, HD)
                     float* __restrict__ Hout,         // (LC*NB, HD)
                     const float* __restrict__ hinit,  // (NB, HD)
                     float* __restrict__ hn)           // (NB, HD)
{
    __shared__ __align__(16) float hs[2][RPC][HD];   // ping-pong full h (16KB)

    const int tid  = threadIdx.x;
    const unsigned int rank = ctarank();             // 0..3
    const int n0   = (blockIdx.x >> 2) * RPC;        // cluster's batch base
    const int slice = (int)rank * COLS_PER_CTA;      // my 128-col W slice

    const int w    = tid >> 5;
    const int lane = tid & 31;
    const int c2   = lane >> 4;            // 0..1
    const int q    = lane & 15;            // 0..15
    const int colw = w * 2 + c2;           // 0..31
    const int myrow = q >> 2;              // 0..3  (batch row in cluster)
    const int mycl  = (q & 3) * 32 + colw; // 0..127 (col within slice)
    const int gcol  = slice + mycl;        // global output column

    const ulonglong2* Wu = (const ulonglong2*)W;     // 16B granules

    // init h(-1) into buffer 0: 4 rows x 512 cols, coalesced
#pragma unroll
    for (int r = 0; r < RPC; r++) {
        int idx = tid + r * RT;            // 0..2047
        int row = idx >> 9, col = idx & 511;
        hs[0][row][col] = __ldg(&hinit[(n0 + row) * HD + col]);
    }

    // preload Apre for t=0 (per-thread own output element)
    float ac = __ldg(&Apre[(size_t)(n0 + myrow) * HD + gcol]);
    __syncthreads();

    int b = 0;
    for (int t = 0; t < LC; t++) {
        // prefetch next step's Apre (independent of everything below)
        const int tn = (t + 1 < LC) ? (t + 1) : t;
        float ap = __ldg(&Apre[((size_t)tn * NB + n0 + myrow) * HD + gcol]);

        // acc[row][cb]: packed (even,odd) k partials
        unsigned long long acc[RPC][4];
#pragma unroll
        for (int r = 0; r < RPC; r++)
#pragma unroll
            for (int cb = 0; cb < 4; cb++) acc[r][cb] = 0ULL;

        const ulonglong2* h0u = (const ulonglong2*)&hs[b][0][0];
        const ulonglong2* h1u = (const ulonglong2*)&hs[b][1][0];
        const ulonglong2* h2u = (const ulonglong2*)&hs[b][2][0];
        const ulonglong2* h3u = (const ulonglong2*)&hs[b][3][0];
#pragma unroll
        for (int ki = 0; ki < 8; ki++) {
            const int k4 = q + 16 * ki;              // float4 index 0..127
            ulonglong2 h0 = h0u[k4];                 // LDS.128, conflict-free
            ulonglong2 h1 = h1u[k4];
            ulonglong2 h2 = h2u[k4];
            ulonglong2 h3 = h3u[k4];
#pragma unroll
            for (int cb = 0; cb < 4; cb++) {
                ulonglong2 wv = __ldg(&Wu[(slice + cb * 32 + colw) * 128 + k4]);
                ffma2(acc[0][cb], wv.x, h0.x); ffma2(acc[0][cb], wv.y, h0.y);
                ffma2(acc[1][cb], wv.x, h1.x); ffma2(acc[1][cb], wv.y, h1.y);
                ffma2(acc[2][cb], wv.x, h2.x); ffma2(acc[2][cb], wv.y, h2.y);
                ffma2(acc[3][cb], wv.x, h3.x); ffma2(acc[3][cb], wv.y, h3.y);
            }
        }

        // merge pairs + reduce across the 16 q-lanes (xor 8,4,2,1)
        float v = 0.f;
#pragma unroll
        for (int r = 0; r < RPC; r++) {
#pragma unroll
            for (int cb = 0; cb < 4; cb++) {
                U64F2 m;
                m.u = acc[r][cb];
                float s = m.f.x + m.f.y;
#pragma unroll
                for (int sh = 8; sh > 0; sh >>= 1)
                    s += __shfl_xor_sync(0xffffffffu, s, sh);
                if (q == r * 4 + cb) v = s;          // predicated keep
            }
        }

        float o = tanhf(v + ac);
        ac = ap;                            // rotate prefetched Apre

        // publish o into hs[b^1][myrow][gcol] of ALL 4 cluster CTAs
        {
            unsigned int base = smem_u32(&hs[b ^ 1][myrow][gcol]);
            hs[b ^ 1][myrow][gcol] = o;     // local copy
#pragma unroll
            for (unsigned int rr = 0; rr < CSZ; rr++)
                if (rr != rank) st_cluster_f32(base, rr, o);
        }
        cluster_sync();                     // release/acquire: h(t) complete

        // flush my slice of h(t) to global (coalesced 512B runs)
        {
            int row = tid >> 7, cl = tid & 127;
            float hv = hs[b ^ 1][row][slice + cl];
            Hout[((size_t)t * NB + n0 + row) * HD + slice + cl] = hv;
            if (t == LC - 1)
                hn[(n0 + row) * HD + slice + cl] = hv;
        }
        b ^= 1;
    }
}

// ---------------- launch: 4 plain nodes ----------------------------------
extern "C" void kernel_launch(void* const* d_in, const int* in_sizes, int n_in,
                              void* d_out, int out_size) {
    const float* input  = (const float*)d_in[0];
    const float* h_0    = (const float*)d_in[1];
    const float* Wih0   = (const float*)d_in[2];
    const float* Whh0   = (const float*)d_in[3];
    const float* bih0   = (const float*)d_in[4];
    const float* bhh0   = (const float*)d_in[5];
    const float* Wih1   = (const float*)d_in[6];
    const float* Whh1   = (const float*)d_in[7];
    const float* bih1   = (const float*)d_in[8];
    const float* bhh1   = (const float*)d_in[9];
    float* out = (float*)d_out;

    float* hn0 = out + (size_t)LC * NB * HD;            // h_n layer 0
    float* hn1 = hn0 + NB * HD;                          // h_n layer 1

    dim3 ggrid(HD / 128, (LC * NB) / 128);               // (4, 256)

    // 1) A0 = x @ Wih0^T + bih0 + bhh0   (parallel)
    gemm_xW_kernel<<<ggrid, 256>>>(input, Wih0, bih0, bhh0, g_A0);

    // 2) layer-0 scan: h0(t) = tanh(A0[t] + Whh0 h0(t-1)); stores all h0(t)
    rnn_pass_kernel<<<RG, RT>>>(Whh0, g_A0, g_H0, h_0, hn0);

    // 3) X1 = H0 @ Wih1^T + bih1 + bhh1  (parallel)
    gemm_xW_kernel<<<ggrid, 256>>>(g_H0, Wih1, bih1, bhh1, g_X1);

    // 4) layer-1 scan: h1(t) = tanh(X1[t] + Whh1 h1(t-1)); writes `out` rows
    rnn_pass_kernel<<<RG, RT>>>(Whh1, g_X1, out, h_0 + NB * HD, hn1);
}